// round 1
// baseline (speedup 1.0000x reference)
#include <cuda_runtime.h>

// Batched 256-point complex DFT, out = FFT(x) / sqrt(256).
// Four-step algorithm: 256 = 16 x 16.
//   n = 16*n2 + n1, k = 16*k1 + k2
//   X[16 k1 + k2] = sum_{n1} W256^{n1 k2} W16^{n1 k1} * ( sum_{n2} x[16 n2 + n1] W16^{n2 k2} )
// 16 threads per frame (thread t = n1 in step 1, t = k2 in step 3),
// 16 frames per 256-thread block. Twiddles are read from row 1 of the
// input W matrix (W[1][c] = W256^c), so numerics match the reference's W.

#define NPT      256
#define FPB      16           // frames per block
#define BLOCK    256
#define ROWS     17           // padded row stride in shared (16+1)
#define FSTRIDE  272          // frame stride in shared; 272 % 32 == 16 -> cross-frame bank disjoint

__device__ __forceinline__ void dft4(
    float& r0, float& i0, float& r1, float& i1,
    float& r2, float& i2, float& r3, float& i3)
{
    // forward 4-pt DFT, W4 = -i
    float t0r = r0 + r2, t0i = i0 + i2;
    float t1r = r0 - r2, t1i = i0 - i2;
    float t2r = r1 + r3, t2i = i1 + i3;
    float t3r = r1 - r3, t3i = i1 - i3;
    r0 = t0r + t2r;  i0 = t0i + t2i;
    r2 = t0r - t2r;  i2 = t0i - t2i;
    r1 = t1r + t3i;  i1 = t1i - t3r;   // t1 - i*t3
    r3 = t1r - t3i;  i3 = t1i + t3r;   // t1 + i*t3
}

// In-register forward 16-pt DFT (two radix-4 stages, DIT).
// Input x[n] natural order. Output X[4*k1 + k2] lives in slot (4*k2 + k1),
// i.e. base-4 digit-reversed; callers remap with rev4().
__device__ __forceinline__ void fft16(float* xr, float* xi,
                                      const float* __restrict__ twR,
                                      const float* __restrict__ twI)
{
    // stage 1: 4-pt DFTs over n2 (stride 4): slots (n1, n1+4, n1+8, n1+12)
#pragma unroll
    for (int n1 = 0; n1 < 4; n1++) {
        dft4(xr[n1],    xi[n1],
             xr[n1+4],  xi[n1+4],
             xr[n1+8],  xi[n1+8],
             xr[n1+12], xi[n1+12]);
    }
    // twiddle: slot n1 + 4*k2 *= W16^{n1*k2} = W256^{16*n1*k2} (broadcast LDS)
#pragma unroll
    for (int n1 = 1; n1 < 4; n1++) {
#pragma unroll
        for (int k2 = 1; k2 < 4; k2++) {
            int s = n1 + 4 * k2;
            int m = 16 * n1 * k2;          // <= 144
            float wr = twR[m], wi = twI[m];
            float ar = xr[s], ai = xi[s];
            xr[s] = ar * wr - ai * wi;
            xi[s] = ar * wi + ai * wr;
        }
    }
    // stage 2: 4-pt DFTs over n1 (stride 1) for each k2
#pragma unroll
    for (int k2 = 0; k2 < 4; k2++) {
        dft4(xr[4*k2+0], xi[4*k2+0],
             xr[4*k2+1], xi[4*k2+1],
             xr[4*k2+2], xi[4*k2+2],
             xr[4*k2+3], xi[4*k2+3]);
    }
}

__device__ __forceinline__ int rev4(int k) { return ((k & 3) << 2) | (k >> 2); }

__global__ void __launch_bounds__(BLOCK)
dft256_kernel(const float* __restrict__ xr, const float* __restrict__ xi,
              const float* __restrict__ Wr, const float* __restrict__ Wi,
              float* __restrict__ outR, float* __restrict__ outI)
{
    __shared__ float twR[NPT], twI[NPT];
    __shared__ float shR[FPB * FSTRIDE], shI[FPB * FSTRIDE];

    const int tid = threadIdx.x;

    // Twiddle table = row 1 of W: W[1][c] = W256^c
    twR[tid] = Wr[NPT + tid];
    twI[tid] = Wi[NPT + tid];
    __syncthreads();

    const int f = tid >> 4;       // frame within block
    const int t = tid & 15;       // lane within frame
    const size_t frame = (size_t)blockIdx.x * FPB + f;
    const float* xrp = xr + frame * NPT;
    const float* xip = xi + frame * NPT;

    // ---- step 1: column DFT (over n2) for n1 = t ----
    float ar[16], ai[16];
#pragma unroll
    for (int n2 = 0; n2 < 16; n2++) {
        ar[n2] = xrp[n2 * 16 + t];
        ai[n2] = xip[n2 * 16 + t];
    }
    fft16(ar, ai, twR, twI);

    // ---- step 2: twiddle W256^{t*k}, transpose to shared [k][n1=t] ----
    float* sR = shR + f * FSTRIDE;
    float* sI = shI + f * FSTRIDE;
#pragma unroll
    for (int k = 0; k < 16; k++) {
        int s = rev4(k);
        float vr = ar[s], vi = ai[s];
        int m = t * k;                 // <= 225
        float wr = twR[m], wi = twI[m];
        sR[k * ROWS + t] = vr * wr - vi * wi;
        sI[k * ROWS + t] = vr * wi + vi * wr;
    }
    __syncthreads();

    // ---- step 3: row DFT (over n1) for k2 = t ----
    float br[16], bi[16];
#pragma unroll
    for (int n1 = 0; n1 < 16; n1++) {
        br[n1] = sR[t * ROWS + n1];
        bi[n1] = sI[t * ROWS + n1];
    }
    fft16(br, bi, twR, twI);

    const float scale = 0.0625f;   // 1/sqrt(256)
    float* orp = outR + frame * NPT;
    float* oip = outI + frame * NPT;
#pragma unroll
    for (int k1 = 0; k1 < 16; k1++) {
        int s = rev4(k1);
        orp[k1 * 16 + t] = br[s] * scale;
        oip[k1 * 16 + t] = bi[s] * scale;
    }
}

extern "C" void kernel_launch(void* const* d_in, const int* in_sizes, int n_in,
                              void* d_out, int out_size)
{
    const float* x_real = (const float*)d_in[0];
    const float* x_imag = (const float*)d_in[1];
    const float* W_real = (const float*)d_in[2];
    const float* W_imag = (const float*)d_in[3];

    const size_t nframes = (size_t)in_sizes[0] / NPT;   // 262144
    float* outR = (float*)d_out;
    float* outI = outR + nframes * NPT;                 // [real | imag] concatenation

    const int grid = (int)(nframes / FPB);              // 16384
    dft256_kernel<<<grid, BLOCK>>>(x_real, x_imag, W_real, W_imag, outR, outI);
}